// round 12
// baseline (speedup 1.0000x reference)
#include <cuda_runtime.h>
#include <cstdint>

// ---------------------------------------------------------------------------
// kernel(i,j) = | prod_k cos((x_ik - y_jk)/2) |
//   = | Px_i * Py_j * prod_k (1 + tx_ik * ty_jk) |,  t = tan(v/2), P = prod cos(v/2)
// SINGLE kernel, no grid barrier: each 128x128 block recomputes its 4096
// (tan, cos) entries (16/thread) with MUFU __sinf/__cosf (+ exact sincosf
// fallback when |cos| < 0.01), then an FMA-bound 8x8-per-thread product loop.
// 128x128 tiles halve phase-A redundancy vs 64x128 and improve LDS:FMA ratio.
// ---------------------------------------------------------------------------

#define D 16
#define TM 128
#define TN 128
#define THREADS 256   // 16x16; each thread: 8 rows x (4+4) cols

typedef unsigned long long u64;

__device__ __forceinline__ u64 pack2(float lo, float hi) {
    u64 r;
    asm("mov.b64 %0, {%1, %2};" : "=l"(r) : "r"(__float_as_uint(lo)), "r"(__float_as_uint(hi)));
    return r;
}
__device__ __forceinline__ void unpack2(u64 v, float& lo, float& hi) {
    unsigned a, b;
    asm("mov.b64 {%0, %1}, %2;" : "=r"(a), "=r"(b) : "l"(v));
    lo = __uint_as_float(a);
    hi = __uint_as_float(b);
}
__device__ __forceinline__ u64 mul2(u64 a, u64 b) {
    u64 r;
    asm("mul.rn.f32x2 %0, %1, %2;" : "=l"(r) : "l"(a), "l"(b));
    return r;
}
__device__ __forceinline__ u64 fma2(u64 a, u64 b, u64 c) {
    u64 r;
    asm("fma.rn.f32x2 %0, %1, %2, %3;" : "=l"(r) : "l"(a), "l"(b), "l"(c));
    return r;
}

__global__ __launch_bounds__(THREADS, 2)
void qk_fused(const float* __restrict__ x, const float* __restrict__ y,
              float* __restrict__ out, int n, int m) {
    __shared__ __align__(16) u64 sxt[D][TM + 2];          // x tans dup (t,t), pitch 130
    __shared__ __align__(16) float syt[D][TN + 4];        // y tans, pitch 132
    __shared__ __align__(16) u64 spx[TM];                 // (Px,Px)
    __shared__ __align__(16) float spy[TN];               // Py
    __shared__ __align__(16) float scc[D][TM + TN + 8];   // cos scratch [k][row]

    const int tid = threadIdx.x;
    const int i0 = blockIdx.y * TM;
    const int j0 = blockIdx.x * TN;

    // ---- phase A: per-block table build (16 elements/thread, no branch div)
    #pragma unroll
    for (int q = 0; q < 8; ++q) {           // x: 2048 elements
        int e = tid + 256 * q;
        int row = e >> 4;
        int k = e & (D - 1);
        float h = 0.5f * x[i0 * D + e];
        float c = __cosf(h);
        float s = __sinf(h);
        if (fabsf(c) < 0.01f) {             // rare exact fallback
            sincosf(h, &s, &c);
            if (fabsf(c) < 1e-20f) c = copysignf(1e-20f, c);
        }
        float t = __fdividef(s, c);
        sxt[k][row] = pack2(t, t);
        scc[k][row] = c;
    }
    #pragma unroll
    for (int q = 0; q < 8; ++q) {           // y: 2048 elements
        int e = tid + 256 * q;
        int row = e >> 4;
        int k = e & (D - 1);
        float h = 0.5f * y[j0 * D + e];
        float c = __cosf(h);
        float s = __sinf(h);
        if (fabsf(c) < 0.01f) {
            sincosf(h, &s, &c);
            if (fabsf(c) < 1e-20f) c = copysignf(1e-20f, c);
        }
        float t = __fdividef(s, c);
        syt[k][row] = t;
        scc[k][TM + row] = c;
    }
    __syncthreads();

    // ---- phase B: row/col cos-products (all 256 threads, conflict-free) ---
    {
        float p = scc[0][tid];
        #pragma unroll
        for (int k = 1; k < D; ++k) p *= scc[k][tid];
        if (tid < TM) spx[tid] = pack2(p, p);
        else spy[tid - TM] = p;
    }
    __syncthreads();

    // ---- main loop: conflict-free, 6 LDS.128 + 64 packed per k ------------
    const int tx = tid & 15;
    const int ty = tid >> 4;
    const int ib = ty * 8;        // even -> 16B-aligned LDS.128 on sxt rows
    const int ja = tx * 4;        // 16B lane stride, conflict-free
    const int jB = 64 + tx * 4;

    const u64 one2 = pack2(1.0f, 1.0f);
    u64 acc[8][4];
    #pragma unroll
    for (int r = 0; r < 8; ++r)
        #pragma unroll
        for (int p = 0; p < 4; ++p)
            acc[r][p] = one2;

    #pragma unroll
    for (int k = 0; k < D; ++k) {
        ulonglong2 ya = *reinterpret_cast<const ulonglong2*>(&syt[k][ja]);
        ulonglong2 yb = *reinterpret_cast<const ulonglong2*>(&syt[k][jB]);
        #pragma unroll
        for (int h = 0; h < 4; ++h) {       // 2 rows per LDS.128
            ulonglong2 xp = *reinterpret_cast<const ulonglong2*>(&sxt[k][ib + 2 * h]);
            u64 x0 = xp.x, x1 = xp.y;
            int r = 2 * h;
            acc[r][0] = fma2(acc[r][0], mul2(x0, ya.x), acc[r][0]);
            acc[r][1] = fma2(acc[r][1], mul2(x0, ya.y), acc[r][1]);
            acc[r][2] = fma2(acc[r][2], mul2(x0, yb.x), acc[r][2]);
            acc[r][3] = fma2(acc[r][3], mul2(x0, yb.y), acc[r][3]);
            acc[r+1][0] = fma2(acc[r+1][0], mul2(x1, ya.x), acc[r+1][0]);
            acc[r+1][1] = fma2(acc[r+1][1], mul2(x1, ya.y), acc[r+1][1]);
            acc[r+1][2] = fma2(acc[r+1][2], mul2(x1, yb.x), acc[r+1][2]);
            acc[r+1][3] = fma2(acc[r+1][3], mul2(x1, yb.y), acc[r+1][3]);
        }
    }

    // ---- epilogue: scale by Px*Py, abs, two coalesced float4 stores/row ---
    ulonglong2 pya = *reinterpret_cast<const ulonglong2*>(&spy[ja]);
    ulonglong2 pyb = *reinterpret_cast<const ulonglong2*>(&spy[jB]);
    #pragma unroll
    for (int r = 0; r < 8; ++r) {
        u64 px2 = spx[ib + r];
        u64 v0 = mul2(mul2(acc[r][0], px2), pya.x);
        u64 v1 = mul2(mul2(acc[r][1], px2), pya.y);
        u64 v2 = mul2(mul2(acc[r][2], px2), pyb.x);
        u64 v3 = mul2(mul2(acc[r][3], px2), pyb.y);
        float a0, a1, b0, b1, c0, c1, d0, d1;
        unpack2(v0, a0, a1);
        unpack2(v1, b0, b1);
        unpack2(v2, c0, c1);
        unpack2(v3, d0, d1);
        float* row = &out[(size_t)(i0 + ib + r) * m + j0];
        *reinterpret_cast<float4*>(row + ja) =
            make_float4(fabsf(a0), fabsf(a1), fabsf(b0), fabsf(b1));
        *reinterpret_cast<float4*>(row + jB) =
            make_float4(fabsf(c0), fabsf(c1), fabsf(d0), fabsf(d1));
    }
}

// ---------------------------------------------------------------------------
extern "C" void kernel_launch(void* const* d_in, const int* in_sizes, int n_in,
                              void* d_out, int out_size) {
    const float* x = (const float*)d_in[0];
    const float* y = (const float*)d_in[1];
    float* out = (float*)d_out;

    int nx = in_sizes[0];      // n * D
    int ny = in_sizes[1];      // m * D
    int n = nx / D;
    int m = ny / D;

    dim3 grid(m / TN, n / TM);
    qk_fused<<<grid, THREADS>>>(x, y, out, n, m);
}

// round 13
// speedup vs baseline: 1.0345x; 1.0345x over previous
#include <cuda_runtime.h>
#include <cstdint>

// ---------------------------------------------------------------------------
// kernel(i,j) = | prod_k cos((x_ik - y_jk)/2) |
//   = | Px_i * Py_j * prod_k (1 + tx_ik * ty_jk) |,  t = tan(v/2), P = prod cos(v/2)
// prep_y (PDL primary): exact tan/cos-product tables for y (32K elems).
//   Signals launch_dependents at its TOP so the main grid launches and runs
//   its independent x-phase concurrently; main's griddepcontrol.wait gates
//   only the y-table reads.
// qk_main (PDL dependent): x tables computed locally per block (1024 MUFU
//   sincos + exact fallback), Px products, wait, y fill from global, then the
//   R7-proven conflict-free 64x128 f32x2 mainloop.
// ---------------------------------------------------------------------------

#define D 16
#define TM 64
#define TN 128
#define THREADS 256   // 16x16; each thread: 4 rows x (4+4) cols

__device__ float g_ty[4096 * D];
__device__ float g_py[4096];

typedef unsigned long long u64;

__device__ __forceinline__ u64 pack2(float lo, float hi) {
    u64 r;
    asm("mov.b64 %0, {%1, %2};" : "=l"(r) : "r"(__float_as_uint(lo)), "r"(__float_as_uint(hi)));
    return r;
}
__device__ __forceinline__ void unpack2(u64 v, float& lo, float& hi) {
    unsigned a, b;
    asm("mov.b64 {%0, %1}, %2;" : "=r"(a), "=r"(b) : "l"(v));
    lo = __uint_as_float(a);
    hi = __uint_as_float(b);
}
__device__ __forceinline__ u64 mul2(u64 a, u64 b) {
    u64 r;
    asm("mul.rn.f32x2 %0, %1, %2;" : "=l"(r) : "l"(a), "l"(b));
    return r;
}
__device__ __forceinline__ u64 fma2(u64 a, u64 b, u64 c) {
    u64 r;
    asm("fma.rn.f32x2 %0, %1, %2, %3;" : "=l"(r) : "l"(a), "l"(b), "l"(c));
    return r;
}

// ---------------------------------------------------------------------------
// PDL primary: y tables (exact sincosf — fully overlapped, cost irrelevant).
// ---------------------------------------------------------------------------
__global__ void prep_y(const float* __restrict__ y, int ny) {
    // Allow dependents to launch immediately; they wait before reading tables.
    asm volatile("griddepcontrol.launch_dependents;" ::: "memory");

    int t = blockIdx.x * blockDim.x + threadIdx.x;
    bool live = t < ny;
    float v = live ? y[t] : 0.0f;
    float s, c;
    sincosf(0.5f * v, &s, &c);
    if (fabsf(c) < 1e-20f) c = copysignf(1e-20f, c);
    float tn = s / c;
    float p = c;
    p *= __shfl_xor_sync(0xffffffffu, p, 1);
    p *= __shfl_xor_sync(0xffffffffu, p, 2);
    p *= __shfl_xor_sync(0xffffffffu, p, 4);
    p *= __shfl_xor_sync(0xffffffffu, p, 8);
    if (live) {
        g_ty[t] = tn;
        if ((t & (D - 1)) == 0) g_py[t >> 4] = p;
    }
}

// ---------------------------------------------------------------------------
// PDL dependent: local x phase, wait, y fill, mainloop.
// ---------------------------------------------------------------------------
__global__ __launch_bounds__(THREADS, 4)
void qk_main(const float* __restrict__ x, float* __restrict__ out, int n, int m) {
    __shared__ __align__(16) u64 sxt[D][TM + 2];     // x tans dup (t,t), pitch 66
    __shared__ __align__(16) float syt[D][TN + 4];   // y tans, pitch 132
    __shared__ __align__(16) u64 spx[TM];            // (Px,Px)
    __shared__ __align__(16) float spy[TN];          // Py
    __shared__ __align__(16) float scc[D][TM + 2];   // x cos scratch

    const int tid = threadIdx.x;
    const int i0 = blockIdx.y * TM;
    const int j0 = blockIdx.x * TN;

    // ---- phase A (independent of prep_y): x tables, 4 elems/thread --------
    #pragma unroll
    for (int q = 0; q < 4; ++q) {
        int e = tid + 256 * q;          // 0..1023; coalesced
        int row = e >> 4;
        int k = e & (D - 1);
        float h = 0.5f * x[i0 * D + e];
        float c = __cosf(h);
        float s = __sinf(h);
        if (fabsf(c) < 0.01f) {         // rare exact fallback near cos zero
            sincosf(h, &s, &c);
            if (fabsf(c) < 1e-20f) c = copysignf(1e-20f, c);
        }
        float t = __fdividef(s, c);
        sxt[k][row] = pack2(t, t);
        scc[k][row] = c;
    }
    __syncthreads();
    if (tid < TM) {                      // Px products
        float p = scc[0][tid];
        #pragma unroll
        for (int k = 1; k < D; ++k) p *= scc[k][tid];
        spx[tid] = pack2(p, p);
    }

    // ---- gate on prep_y completion, then fill y smem ----------------------
    asm volatile("griddepcontrol.wait;" ::: "memory");

    #pragma unroll
    for (int idx = tid; idx < TN * D; idx += THREADS) {
        int j = idx >> 4;
        int k = idx & (D - 1);
        syt[k][j] = g_ty[j0 * D + idx];
    }
    if (tid >= TM && tid < TM + TN) {
        spy[tid - TM] = g_py[j0 + tid - TM];
    }
    __syncthreads();

    // ---- main loop (R7-proven conflict-free config) -----------------------
    const int tx = tid & 15;
    const int ty = tid >> 4;
    const int ib = ty * 4;        // even -> 16B-aligned LDS.128 on sxt rows
    const int ja = tx * 4;        // 16B lane stride, conflict-free
    const int jB = 64 + tx * 4;

    const u64 one2 = pack2(1.0f, 1.0f);
    u64 acc[4][4];
    #pragma unroll
    for (int r = 0; r < 4; ++r)
        #pragma unroll
        for (int p = 0; p < 4; ++p)
            acc[r][p] = one2;

    #pragma unroll
    for (int k = 0; k < D; ++k) {
        ulonglong2 ya = *reinterpret_cast<const ulonglong2*>(&syt[k][ja]);
        ulonglong2 yb = *reinterpret_cast<const ulonglong2*>(&syt[k][jB]);
        ulonglong2 xa = *reinterpret_cast<const ulonglong2*>(&sxt[k][ib]);
        ulonglong2 xb = *reinterpret_cast<const ulonglong2*>(&sxt[k][ib + 2]);
        u64 xt0 = xa.x, xt1 = xa.y, xt2 = xb.x, xt3 = xb.y;
        acc[0][0] = fma2(acc[0][0], mul2(xt0, ya.x), acc[0][0]);
        acc[0][1] = fma2(acc[0][1], mul2(xt0, ya.y), acc[0][1]);
        acc[0][2] = fma2(acc[0][2], mul2(xt0, yb.x), acc[0][2]);
        acc[0][3] = fma2(acc[0][3], mul2(xt0, yb.y), acc[0][3]);
        acc[1][0] = fma2(acc[1][0], mul2(xt1, ya.x), acc[1][0]);
        acc[1][1] = fma2(acc[1][1], mul2(xt1, ya.y), acc[1][1]);
        acc[1][2] = fma2(acc[1][2], mul2(xt1, yb.x), acc[1][2]);
        acc[1][3] = fma2(acc[1][3], mul2(xt1, yb.y), acc[1][3]);
        acc[2][0] = fma2(acc[2][0], mul2(xt2, ya.x), acc[2][0]);
        acc[2][1] = fma2(acc[2][1], mul2(xt2, ya.y), acc[2][1]);
        acc[2][2] = fma2(acc[2][2], mul2(xt2, yb.x), acc[2][2]);
        acc[2][3] = fma2(acc[2][3], mul2(xt2, yb.y), acc[2][3]);
        acc[3][0] = fma2(acc[3][0], mul2(xt3, ya.x), acc[3][0]);
        acc[3][1] = fma2(acc[3][1], mul2(xt3, ya.y), acc[3][1]);
        acc[3][2] = fma2(acc[3][2], mul2(xt3, yb.x), acc[3][2]);
        acc[3][3] = fma2(acc[3][3], mul2(xt3, yb.y), acc[3][3]);
    }

    // ---- epilogue: scale by Px*Py, abs, two coalesced float4 stores/row ---
    ulonglong2 pya = *reinterpret_cast<const ulonglong2*>(&spy[ja]);
    ulonglong2 pyb = *reinterpret_cast<const ulonglong2*>(&spy[jB]);
    #pragma unroll
    for (int r = 0; r < 4; ++r) {
        u64 px2 = spx[ib + r];
        u64 v0 = mul2(mul2(acc[r][0], px2), pya.x);
        u64 v1 = mul2(mul2(acc[r][1], px2), pya.y);
        u64 v2 = mul2(mul2(acc[r][2], px2), pyb.x);
        u64 v3 = mul2(mul2(acc[r][3], px2), pyb.y);
        float a0, a1, b0, b1, c0, c1, d0, d1;
        unpack2(v0, a0, a1);
        unpack2(v1, b0, b1);
        unpack2(v2, c0, c1);
        unpack2(v3, d0, d1);
        float* row = &out[(size_t)(i0 + ib + r) * m + j0];
        *reinterpret_cast<float4*>(row + ja) =
            make_float4(fabsf(a0), fabsf(a1), fabsf(b0), fabsf(b1));
        *reinterpret_cast<float4*>(row + jB) =
            make_float4(fabsf(c0), fabsf(c1), fabsf(d0), fabsf(d1));
    }
}

// ---------------------------------------------------------------------------
extern "C" void kernel_launch(void* const* d_in, const int* in_sizes, int n_in,
                              void* d_out, int out_size) {
    const float* x = (const float*)d_in[0];
    const float* y = (const float*)d_in[1];
    float* out = (float*)d_out;

    int nx = in_sizes[0];      // n * D
    int ny = in_sizes[1];      // m * D
    int n = nx / D;
    int m = ny / D;

    prep_y<<<(ny + 255) / 256, 256>>>(y, ny);

    cudaLaunchConfig_t cfg = {};
    cfg.gridDim = dim3(m / TN, n / TM);
    cfg.blockDim = dim3(THREADS);
    cfg.dynamicSmemBytes = 0;
    cfg.stream = 0;
    cudaLaunchAttribute attr[1];
    attr[0].id = cudaLaunchAttributeProgrammaticStreamSerialization;
    attr[0].val.programmaticStreamSerializationAllowed = 1;
    cfg.attrs = attr;
    cfg.numAttrs = 1;
    cudaLaunchKernelEx(&cfg, qk_main, x, out, n, m);
}

// round 14
// speedup vs baseline: 1.1189x; 1.0816x over previous
#include <cuda_runtime.h>
#include <cstdint>

// ---------------------------------------------------------------------------
// kernel(i,j) = | prod_k cos((x_ik - y_jk)/2) |
//   = | Px_i * Py_j * prod_k (1 + tx_ik * ty_jk) |,  t = tan(v/2), P = prod cos(v/2)
// prep (PDL primary, MUFU fast path + exact fallback): tan tables and
//   cos-products for BOTH x and y; signals launch_dependents at its top.
// qk_kernel (PDL dependent): griddepcontrol.wait, then the R7-proven
//   conflict-free 64x128 f32x2 mainloop (best measured body: 10.8 us).
// ---------------------------------------------------------------------------

#define D 16
#define TM 64
#define TN 128
#define THREADS 256   // 16x16; each thread: 4 rows x (4+4) cols

__device__ float g_tx[4096 * D];
__device__ float g_ty[4096 * D];
__device__ float g_px[4096];
__device__ float g_py[4096];

typedef unsigned long long u64;

__device__ __forceinline__ u64 pack2(float lo, float hi) {
    u64 r;
    asm("mov.b64 %0, {%1, %2};" : "=l"(r) : "r"(__float_as_uint(lo)), "r"(__float_as_uint(hi)));
    return r;
}
__device__ __forceinline__ void unpack2(u64 v, float& lo, float& hi) {
    unsigned a, b;
    asm("mov.b64 {%0, %1}, %2;" : "=r"(a), "=r"(b) : "l"(v));
    lo = __uint_as_float(a);
    hi = __uint_as_float(b);
}
__device__ __forceinline__ u64 mul2(u64 a, u64 b) {
    u64 r;
    asm("mul.rn.f32x2 %0, %1, %2;" : "=l"(r) : "l"(a), "l"(b));
    return r;
}
__device__ __forceinline__ u64 fma2(u64 a, u64 b, u64 c) {
    u64 r;
    asm("fma.rn.f32x2 %0, %1, %2, %3;" : "=l"(r) : "l"(a), "l"(b), "l"(c));
    return r;
}

// ---------------------------------------------------------------------------
// PDL primary: both tables. MUFU __sinf/__cosf + exact sincosf fallback when
// |cos| < 0.01 (keeps elementwise error ~3.6e-5 worst case, typ ~1e-6).
// Consistent c feeds both tan and the cos-product -> reconstruction exact.
// ---------------------------------------------------------------------------
__global__ void prep(const float* __restrict__ x, const float* __restrict__ y,
                     int nx, int ny) {
    // Let the dependent grid launch & ramp now; its griddepcontrol.wait
    // blocks until THIS grid fully completes (correctness gate).
    asm volatile("griddepcontrol.launch_dependents;" ::: "memory");

    int t = blockIdx.x * blockDim.x + threadIdx.x;
    int total = nx + ny;
    bool live = t < total;
    bool inx = t < nx;
    int u = inx ? t : t - nx;
    float v = 0.0f;
    if (live) v = inx ? x[t] : y[u];
    float h = 0.5f * v;
    float c = __cosf(h);
    float s = __sinf(h);
    if (fabsf(c) < 0.01f) {              // rare exact fallback near cos zero
        sincosf(h, &s, &c);
        if (fabsf(c) < 1e-20f) c = copysignf(1e-20f, c);
    }
    float tn = __fdividef(s, c);
    float p = c;
    p *= __shfl_xor_sync(0xffffffffu, p, 1);
    p *= __shfl_xor_sync(0xffffffffu, p, 2);
    p *= __shfl_xor_sync(0xffffffffu, p, 4);
    p *= __shfl_xor_sync(0xffffffffu, p, 8);
    if (live) {
        if (inx) g_tx[u] = tn; else g_ty[u] = tn;
        if ((u & (D - 1)) == 0) {
            int row = u >> 4;
            if (inx) g_px[row] = p; else g_py[row] = p;
        }
    }
}

// ---------------------------------------------------------------------------
// PDL dependent: R7 mainloop verbatim, gated by griddepcontrol.wait.
// ---------------------------------------------------------------------------
__global__ __launch_bounds__(THREADS, 4)
void qk_kernel(float* __restrict__ out, int n, int m) {
    __shared__ __align__(16) u64 sxt[D][TM + 2];     // x tans dup (t,t), pitch 66
    __shared__ __align__(16) float syt[D][TN + 4];   // y tans, pitch 132
    __shared__ __align__(16) u64 spx[TM];
    __shared__ __align__(16) float spy[TN];

    const int tid = threadIdx.x;
    const int i0 = blockIdx.y * TM;
    const int j0 = blockIdx.x * TN;

    // Gate: primary grid (prep) fully complete & visible.
    asm volatile("griddepcontrol.wait;" ::: "memory");

    // ---- fill shared (coalesced global reads) ----
    #pragma unroll
    for (int idx = tid; idx < TM * D; idx += THREADS) {
        int i = idx >> 4;
        int k = idx & (D - 1);
        float vx = g_tx[(i0 + i) * D + k];
        sxt[k][i] = pack2(vx, vx);
    }
    #pragma unroll
    for (int idx = tid; idx < TN * D; idx += THREADS) {
        int j = idx >> 4;
        int k = idx & (D - 1);
        syt[k][j] = g_ty[(j0 + j) * D + k];
    }
    if (tid < TM) {
        float p = g_px[i0 + tid];
        spx[tid] = pack2(p, p);
    } else if (tid < TM + TN) {
        spy[tid - TM] = g_py[j0 + tid - TM];
    }
    __syncthreads();

    const int tx = tid & 15;
    const int ty = tid >> 4;
    const int ib = ty * 4;        // even -> 16B-aligned LDS.128 on sxt rows
    const int ja = tx * 4;        // 16B lane stride, conflict-free
    const int jB = 64 + tx * 4;

    const u64 one2 = pack2(1.0f, 1.0f);
    u64 acc[4][4];
    #pragma unroll
    for (int r = 0; r < 4; ++r)
        #pragma unroll
        for (int p = 0; p < 4; ++p)
            acc[r][p] = one2;

    #pragma unroll
    for (int k = 0; k < D; ++k) {
        ulonglong2 ya = *reinterpret_cast<const ulonglong2*>(&syt[k][ja]);
        ulonglong2 yb = *reinterpret_cast<const ulonglong2*>(&syt[k][jB]);
        ulonglong2 xa = *reinterpret_cast<const ulonglong2*>(&sxt[k][ib]);
        ulonglong2 xb = *reinterpret_cast<const ulonglong2*>(&sxt[k][ib + 2]);
        u64 xt0 = xa.x, xt1 = xa.y, xt2 = xb.x, xt3 = xb.y;
        acc[0][0] = fma2(acc[0][0], mul2(xt0, ya.x), acc[0][0]);
        acc[0][1] = fma2(acc[0][1], mul2(xt0, ya.y), acc[0][1]);
        acc[0][2] = fma2(acc[0][2], mul2(xt0, yb.x), acc[0][2]);
        acc[0][3] = fma2(acc[0][3], mul2(xt0, yb.y), acc[0][3]);
        acc[1][0] = fma2(acc[1][0], mul2(xt1, ya.x), acc[1][0]);
        acc[1][1] = fma2(acc[1][1], mul2(xt1, ya.y), acc[1][1]);
        acc[1][2] = fma2(acc[1][2], mul2(xt1, yb.x), acc[1][2]);
        acc[1][3] = fma2(acc[1][3], mul2(xt1, yb.y), acc[1][3]);
        acc[2][0] = fma2(acc[2][0], mul2(xt2, ya.x), acc[2][0]);
        acc[2][1] = fma2(acc[2][1], mul2(xt2, ya.y), acc[2][1]);
        acc[2][2] = fma2(acc[2][2], mul2(xt2, yb.x), acc[2][2]);
        acc[2][3] = fma2(acc[2][3], mul2(xt2, yb.y), acc[2][3]);
        acc[3][0] = fma2(acc[3][0], mul2(xt3, ya.x), acc[3][0]);
        acc[3][1] = fma2(acc[3][1], mul2(xt3, ya.y), acc[3][1]);
        acc[3][2] = fma2(acc[3][2], mul2(xt3, yb.x), acc[3][2]);
        acc[3][3] = fma2(acc[3][3], mul2(xt3, yb.y), acc[3][3]);
    }

    // ---- epilogue: scale by Px*Py, abs, two coalesced float4 stores/row ---
    ulonglong2 pya = *reinterpret_cast<const ulonglong2*>(&spy[ja]);
    ulonglong2 pyb = *reinterpret_cast<const ulonglong2*>(&spy[jB]);
    #pragma unroll
    for (int r = 0; r < 4; ++r) {
        u64 px2 = spx[ib + r];
        u64 v0 = mul2(mul2(acc[r][0], px2), pya.x);
        u64 v1 = mul2(mul2(acc[r][1], px2), pya.y);
        u64 v2 = mul2(mul2(acc[r][2], px2), pyb.x);
        u64 v3 = mul2(mul2(acc[r][3], px2), pyb.y);
        float a0, a1, b0, b1, c0, c1, d0, d1;
        unpack2(v0, a0, a1);
        unpack2(v1, b0, b1);
        unpack2(v2, c0, c1);
        unpack2(v3, d0, d1);
        float* row = &out[(size_t)(i0 + ib + r) * m + j0];
        *reinterpret_cast<float4*>(row + ja) =
            make_float4(fabsf(a0), fabsf(a1), fabsf(b0), fabsf(b1));
        *reinterpret_cast<float4*>(row + jB) =
            make_float4(fabsf(c0), fabsf(c1), fabsf(d0), fabsf(d1));
    }
}

// ---------------------------------------------------------------------------
extern "C" void kernel_launch(void* const* d_in, const int* in_sizes, int n_in,
                              void* d_out, int out_size) {
    const float* x = (const float*)d_in[0];
    const float* y = (const float*)d_in[1];
    float* out = (float*)d_out;

    int nx = in_sizes[0];      // n * D
    int ny = in_sizes[1];      // m * D
    int n = nx / D;
    int m = ny / D;

    int total = nx + ny;
    prep<<<(total + 255) / 256, 256>>>(x, y, nx, ny);

    cudaLaunchConfig_t cfg = {};
    cfg.gridDim = dim3(m / TN, n / TM);
    cfg.blockDim = dim3(THREADS);
    cfg.dynamicSmemBytes = 0;
    cfg.stream = 0;
    cudaLaunchAttribute attr[1];
    attr[0].id = cudaLaunchAttributeProgrammaticStreamSerialization;
    attr[0].val.programmaticStreamSerializationAllowed = 1;
    cfg.attrs = attr;
    cfg.numAttrs = 1;
    cudaLaunchKernelEx(&cfg, qk_kernel, out, n, m);
}